// round 11
// baseline (speedup 1.0000x reference)
#include <cuda.h>
#include <cuda_runtime.h>
#include <cstdint>

#define Bz 512
#define Iz 512
#define Hz 1024
#define Oz 512
#define Tz 128

#if defined(__CUDA_ARCH__) && \
    (defined(__CUDA_ARCH_FEAT_SM103_ALL) || defined(__CUDA_ARCH_FEAT_SM100_ALL) || \
     defined(__CUDA_ARCH_SPECIFIC__))
#define HAS_TC5 1
#else
#define HAS_TC5 0
#endif

// --------------------------- device scratch ---------------------------------
__device__ float g_jx[Bz * Hz];
__device__ float g_kx[Bz * Hz];
__device__ float g_h0[Bz * Hz];
__device__ float g_hall[(size_t)Tz * Bz * Hz];
__device__ float g_Wjh[Hz * Hz];
__device__ float g_Wkh[Hz * Hz];
__device__ float g_Wo[Oz * Hz];
__device__ unsigned g_flag[4][16];     // [m-group][n-tile] = completed steps

// --------------------------- PTX helpers ------------------------------------
__device__ __forceinline__ uint32_t smem_u32(const void* p) {
    uint32_t a;
    asm("{ .reg .u64 t; cvta.to.shared.u64 t, %1; cvt.u32.u64 %0, t; }"
        : "=r"(a) : "l"(p));
    return a;
}
__device__ __forceinline__ float tf32r(float x) {
    uint32_t u; asm("cvt.rna.tf32.f32 %0, %1;" : "=r"(u) : "f"(x));
    return __uint_as_float(u);
}
__device__ __forceinline__ uint64_t pol_evict_last() {
    uint64_t p;
    asm("createpolicy.fractional.L2::evict_last.b64 %0, 1.0;" : "=l"(p));
    return p;
}
__device__ __forceinline__ float4 ldg_el(const float4* p, uint64_t pol) {
    float4 v;
    asm("ld.global.L2::cache_hint.v4.f32 {%0, %1, %2, %3}, [%4], %5;"
        : "=f"(v.x), "=f"(v.y), "=f"(v.z), "=f"(v.w) : "l"(p), "l"(pol));
    return v;
}

#define CP16(dst, src) \
    asm volatile("cp.async.cg.shared.global [%0], [%1], 16;" :: "r"(dst), "l"(src) : "memory")
#define CPA_ARRIVE(mb) \
    asm volatile("cp.async.mbarrier.arrive.noinc.shared::cta.b64 [%0];" :: "r"(mb) : "memory")
#define FENCE_ASYNC() asm volatile("fence.proxy.async.shared::cta;" ::: "memory")

#define MBAR_INIT(mb, cnt) \
    asm volatile("mbarrier.init.shared.b64 [%0], %1;" :: "r"(mb), "r"((uint32_t)(cnt)) : "memory")
#define MBAR_INVAL(mb) \
    asm volatile("mbarrier.inval.shared.b64 [%0];" :: "r"(mb) : "memory")
#define MBAR_EXPECT_TX(mb, bytes) \
    asm volatile("mbarrier.arrive.expect_tx.shared.b64 _, [%0], %1;" \
                 :: "r"(mb), "r"((uint32_t)(bytes)) : "memory")
#define MBAR_ARRIVE(mb) \
    asm volatile("mbarrier.arrive.shared.b64 _, [%0];" :: "r"(mb) : "memory")

#define MBAR_WAIT(mb, par) do {                                                  \
    uint32_t _m = (mb), _p = (par), _d;                                          \
    asm volatile("{\n\t.reg .pred p;\n\t"                                        \
        "mbarrier.try_wait.parity.acquire.cta.shared::cta.b64 p, [%1], %2;\n\t"  \
        "selp.b32 %0, 1, 0, p;\n\t}" : "=r"(_d) : "r"(_m), "r"(_p) : "memory");  \
    if (!_d) {                                                                   \
        asm volatile("{\n\t.reg .pred P1;\n\t"                                   \
        "WL_%=:\n\t"                                                             \
        "mbarrier.try_wait.parity.acquire.cta.shared::cta.b64 P1, [%0], %1, 0x989680;\n\t" \
        "@P1 bra.uni WD_%=;\n\t"                                                 \
        "bra.uni WL_%=;\n\t"                                                     \
        "WD_%=:\n\t}" :: "r"(_m), "r"(_p) : "memory");                           \
    }                                                                            \
} while (0)

#define TMA2D_EL(dst, map, x, y, mb, pol) \
    asm volatile("cp.async.bulk.tensor.2d.shared::cta.global.tile.mbarrier::complete_tx::bytes.L2::cache_hint " \
                 "[%0], [%1, {%2, %3}], [%4], %5;" \
                 :: "r"(dst), "l"(map), "r"((int)(x)), "r"((int)(y)), "r"(mb), "l"(pol) \
                 : "memory")

__device__ __forceinline__ void tc_alloc(uint32_t sa, uint32_t n) {
#if HAS_TC5
    asm volatile("tcgen05.alloc.cta_group::1.sync.aligned.shared::cta.b32 [%0], %1;"
                 :: "r"(sa), "r"(n) : "memory");
    asm volatile("tcgen05.relinquish_alloc_permit.cta_group::1.sync.aligned;");
#endif
}
__device__ __forceinline__ void tc_dealloc(uint32_t t, uint32_t n) {
#if HAS_TC5
    asm volatile("tcgen05.dealloc.cta_group::1.sync.aligned.b32 %0, %1;" :: "r"(t), "r"(n));
#endif
}
__device__ __forceinline__ void tc_commit(uint32_t mb) {
#if HAS_TC5
    asm volatile("tcgen05.commit.cta_group::1.mbarrier::arrive::one.shared::cluster.b64 [%0];"
                 :: "r"(mb) : "memory");
#endif
}
__device__ __forceinline__ void tc_fence_after() {
#if HAS_TC5
    asm volatile("tcgen05.fence::after_thread_sync;" ::: "memory");
#endif
}
__device__ __forceinline__ void tc_fence_before() {
#if HAS_TC5
    asm volatile("tcgen05.fence::before_thread_sync;" ::: "memory");
#endif
}
__device__ __forceinline__ void tc_wait_ld() {
#if HAS_TC5
    asm volatile("tcgen05.wait::ld.sync.aligned;" ::: "memory");
#endif
}
__device__ __forceinline__ void tc_ld32(uint32_t* r, uint32_t ta) {
#if HAS_TC5
    asm volatile("tcgen05.ld.sync.aligned.32x32b.x32.b32 "
        "{%0, %1, %2, %3, %4, %5, %6, %7, %8, %9, %10, %11, %12, %13, %14, %15,"
        " %16, %17, %18, %19, %20, %21, %22, %23, %24, %25, %26, %27, %28, %29, %30, %31}, [%32];"
        : "=r"(r[0]),  "=r"(r[1]),  "=r"(r[2]),  "=r"(r[3]),
          "=r"(r[4]),  "=r"(r[5]),  "=r"(r[6]),  "=r"(r[7]),
          "=r"(r[8]),  "=r"(r[9]),  "=r"(r[10]), "=r"(r[11]),
          "=r"(r[12]), "=r"(r[13]), "=r"(r[14]), "=r"(r[15]),
          "=r"(r[16]), "=r"(r[17]), "=r"(r[18]), "=r"(r[19]),
          "=r"(r[20]), "=r"(r[21]), "=r"(r[22]), "=r"(r[23]),
          "=r"(r[24]), "=r"(r[25]), "=r"(r[26]), "=r"(r[27]),
          "=r"(r[28]), "=r"(r[29]), "=r"(r[30]), "=r"(r[31])
        : "r"(ta));
#else
    #pragma unroll
    for (int i = 0; i < 32; ++i) r[i] = 0;
#endif
}
__device__ __forceinline__ void mma_tf32(uint32_t d, uint64_t ad, uint64_t bd,
                                         uint32_t idesc, uint32_t en) {
#if HAS_TC5
    asm volatile(
        "{\n\t.reg .pred p;\n\tsetp.ne.u32 p, %5, 0;\n\t"
        "tcgen05.mma.cta_group::1.kind::tf32 [%0], %1, %2, %3, {%4, %4, %4, %4}, p;\n\t}"
        :: "r"(d), "l"(ad), "l"(bd), "r"(idesc), "r"(0u), "r"(en) : "memory");
#endif
}

__device__ __forceinline__ uint64_t mkdesc(uint32_t addr) {
    constexpr uint64_t BASE =
        (2ull << 61) | (1ull << 46) | (64ull << 32) | (1ull << 16);
    return BASE | ((uint64_t)(addr >> 4) & 0x3FFF);
}

__device__ __forceinline__ float sigm(float x) {
    return 1.0f / (1.0f + __expf(-x));
}

// --------------------------- setup kernels -----------------------------------
__global__ void reset_flags() {
    if (threadIdx.x < 64) g_flag[threadIdx.x >> 4][threadIdx.x & 15] = 0;
}

__global__ void round_weights(const float* __restrict__ Wjh,
                              const float* __restrict__ Wkh,
                              const float* __restrict__ Wo) {
    for (int i = blockIdx.x * blockDim.x + threadIdx.x; i < Hz * Hz;
         i += gridDim.x * blockDim.x) {
        g_Wjh[i] = tf32r(Wjh[i]);
        g_Wkh[i] = tf32r(Wkh[i]);
        if (i < Oz * Hz) g_Wo[i] = tf32r(Wo[i]);
    }
}

// ================= persistent recurrence kernel ==============================
// grid (16, 4) = 64 CTAs. KC=64, 3-stage ring. Fine-grained per-chunk gating
// (flag[grp][c] published by CTA c of the group). L2 policy: weights + jx/kx
// loaded evict_last (pin hot set against the g_hall write stream).
//   warps 0-7 : A producers (cp.async) + epilogue + flag publish
//   tid 256   : weight TMA producer (evict_last, free-running on empty ring)
//   tid 288   : MMA issuer
//   tid 320   : gate — batched flag refresh (16-wide MLP), arrives gate ring
__global__ void __launch_bounds__(352, 1)
rec_persist(const __grid_constant__ CUtensorMap tmWj,
            const __grid_constant__ CUtensorMap tmWk) {
    constexpr int KC = 64;
    constexpr int NC = Hz / KC;        // 16 chunks/step
    constexpr int S  = 3;
    constexpr int SG = 4;              // gate ring slots
    constexpr uint32_t STG = 65536;    // A 32K + B 32K
    constexpr uint32_t OFF = 1024;
    constexpr uint32_t IDESC =         // M=128, N=128, tf32
        (8u << 24) | (16u << 17) | (2u << 10) | (2u << 7) | (1u << 4);

    extern __shared__ __align__(1024) char smem[];
    const uint32_t sb = smem_u32(smem);
    const int tid = threadIdx.x;
    const int wid = tid >> 5, lid = tid & 31;
    const int m0 = blockIdx.y * 128;
    const int n0 = blockIdx.x * 64;
    const int grp = blockIdx.y;
    const int myN = blockIdx.x;

    if (wid == 0) tc_alloc(sb + 0, 128);
    if (tid == 0) {
        #pragma unroll
        for (int s = 0; s < S; ++s) {
            MBAR_INIT(sb + 16 + 16 * s, 257);   // full[s]: 256 A + 1 expect_tx
            MBAR_INIT(sb + 24 + 16 * s, 1);     // empty[s]: tcgen05.commit
        }
        #pragma unroll
        for (int i = 0; i < SG; ++i)
            MBAR_INIT(sb + 80 + 8 * i, 1);      // gate[i]
    }
    __syncthreads();
    uint32_t tb;
    asm volatile("ld.shared.b32 %0, [%1];" : "=r"(tb) : "r"(sb + 0));

    if (tid < 256) {
        // ========== A producers + epilogue ==========
        const uint64_t pel = pol_evict_last();
        const int sub = wid & 3, g = wid >> 2;
        const int m = m0 + sub * 32 + lid;
        const int n = n0 + g * 32;
        const float4* jx4 = (const float4*)(g_jx + (size_t)m * Hz + n);
        const float4* kx4 = (const float4*)(g_kx + (size_t)m * Hz + n);

        float4 hreg[8];
        {
            const float4* h04 = (const float4*)(g_h0 + (size_t)m * Hz + n);
            #pragma unroll
            for (int v = 0; v < 8; ++v) hreg[v] = h04[v];
        }

        for (int t = 0; t < Tz; ++t) {
            const float* Arow = ((t == 0) ? g_h0
                                          : g_hall + (size_t)(t - 1) * Bz * Hz)
                                + (size_t)m0 * Hz;
            for (int c = 0; c < NC; ++c) {
                const int C = t * NC + c;
                MBAR_WAIT(sb + 80 + 8 * (C % SG), (C / SG) & 1);
                const int s = C % S;
                if (C >= S) MBAR_WAIT(sb + 24 + 16 * s, ((C / S) - 1) & 1);
                const uint32_t base = sb + OFF + s * STG;
                const int k0 = c * KC;
                #pragma unroll
                for (int i = 0; i < 8; ++i) {          // A: 128 rows x 64 f32
                    int v = i * 256 + tid;
                    int row = v >> 4, kk = (v & 15) << 2;
                    uint32_t off = (uint32_t)(row << 7) + ((kk & 31) << 2);
                    off ^= (off >> 3) & 0x70;
                    CP16(base + (uint32_t)((kk >> 5) * 16384) + off,
                         Arow + (size_t)row * Hz + k0 + kk);
                }
                CPA_ARRIVE(sb + 16 + 16 * s);
            }

            // ---- epilogue ----
            float4 jxv[8], kxv[8];
            #pragma unroll
            for (int v = 0; v < 8; ++v) {
                jxv[v] = ldg_el(jx4 + v, pel);
                kxv[v] = ldg_el(kx4 + v, pel);
            }

            const int CL = t * NC + (NC - 1);
            MBAR_WAIT(sb + 24 + 16 * (CL % S), (CL / S) & 1);
            tc_fence_after();

            uint32_t jr[32], kr[32];
            tc_ld32(jr, tb + g * 32);
            tc_ld32(kr, tb + 64 + g * 32);
            tc_wait_ld();

            float* hop = g_hall + (size_t)t * Bz * Hz + (size_t)m * Hz + n;
            #pragma unroll
            for (int v = 0; v < 8; ++v) {
                float4 jx = jxv[v], kx = kxv[v], hp = hreg[v], o;
                {
                    float jg = sigm(jx.x + __uint_as_float(jr[4 * v + 0]));
                    float kg = sigm(kx.x + __uint_as_float(kr[4 * v + 0]));
                    o.x = tf32r(jg + hp.x * (1.0f - jg - kg));
                }
                {
                    float jg = sigm(jx.y + __uint_as_float(jr[4 * v + 1]));
                    float kg = sigm(kx.y + __uint_as_float(kr[4 * v + 1]));
                    o.y = tf32r(jg + hp.y * (1.0f - jg - kg));
                }
                {
                    float jg = sigm(jx.z + __uint_as_float(jr[4 * v + 2]));
                    float kg = sigm(kx.z + __uint_as_float(kr[4 * v + 2]));
                    o.z = tf32r(jg + hp.z * (1.0f - jg - kg));
                }
                {
                    float jg = sigm(jx.w + __uint_as_float(jr[4 * v + 3]));
                    float kg = sigm(kx.w + __uint_as_float(kr[4 * v + 3]));
                    o.w = tf32r(jg + hp.w * (1.0f - jg - kg));
                }
                ((float4*)hop)[v] = o;
                hreg[v] = o;
            }
            tc_fence_before();

            // ---- publish my h columns for step t ----
            asm volatile("bar.sync 1, 256;" ::: "memory");
            if (tid == 0) {
                __threadfence();
                asm volatile("st.release.gpu.global.u32 [%0], %1;"
                             :: "l"(&g_flag[grp][myN]), "r"((unsigned)(t + 1))
                             : "memory");
            }
        }
    } else if (tid == 256) {
        // ========== weight producer: TMA evict_last, free-running ==========
        const uint64_t pel = pol_evict_last();
        for (int t = 0; t < Tz; ++t) {
            for (int c = 0; c < NC; ++c) {
                const int C = t * NC + c;
                const int s = C % S;
                if (C >= S) MBAR_WAIT(sb + 24 + 16 * s, ((C / S) - 1) & 1);
                const uint32_t base = sb + OFF + s * STG;
                const uint32_t fb = sb + 16 + 16 * s;
                const int k0 = c * KC;
                MBAR_EXPECT_TX(fb, 32768);
                TMA2D_EL(base + 32768,        &tmWj, k0,      n0, fb, pel);
                TMA2D_EL(base + 32768 + 8192, &tmWk, k0,      n0, fb, pel);
                TMA2D_EL(base + 49152,        &tmWj, k0 + 32, n0, fb, pel);
                TMA2D_EL(base + 49152 + 8192, &tmWk, k0 + 32, n0, fb, pel);
            }
        }
    } else if (tid == 288) {
        // ========== MMA issuer ==========
        for (int t = 0; t < Tz; ++t) {
            for (int c = 0; c < NC; ++c) {
                const int C = t * NC + c;
                const int s = C % S;
                MBAR_WAIT(sb + 16 + 16 * s, (C / S) & 1);
                FENCE_ASYNC();
                const uint32_t base = sb + OFF + s * STG;
                #pragma unroll
                for (int s2 = 0; s2 < 2; ++s2) {
                    const uint64_t ad = mkdesc(base + s2 * 16384);
                    const uint64_t bd = mkdesc(base + 32768 + s2 * 16384);
                    #pragma unroll
                    for (int q = 0; q < 4; ++q) {
                        uint32_t en = (c | s2 | q) != 0;
                        mma_tf32(tb, ad + q * 2, bd + q * 2, IDESC, en);
                    }
                }
                tc_commit(sb + 24 + 16 * s);
            }
        }
    } else if (tid == 320) {
        // ========== gate: batched flag refresh, arrive per chunk ==========
        unsigned fc[16];
        #pragma unroll
        for (int i = 0; i < 16; ++i) fc[i] = 0;
        for (int t = 0; t < Tz; ++t) {
            for (int c = 0; c < NC; ++c) {
                const int C = t * NC + c;
                const int s = C % S;
                if (C >= S) MBAR_WAIT(sb + 24 + 16 * s, ((C / S) - 1) & 1);
                if (t > 0) {
                    while (fc[c] < (unsigned)t) {
                        #pragma unroll
                        for (int i = 0; i < 16; ++i)
                            asm volatile("ld.acquire.gpu.global.u32 %0, [%1];"
                                         : "=r"(fc[i]) : "l"(&g_flag[grp][i])
                                         : "memory");
                        if (fc[c] < (unsigned)t) __nanosleep(64);
                    }
                }
                MBAR_ARRIVE(sb + 80 + 8 * (C % SG));
            }
        }
    }

    __syncthreads();
    if (tid == 0) {
        #pragma unroll
        for (int s = 0; s < S; ++s) {
            MBAR_INVAL(sb + 16 + 16 * s);
            MBAR_INVAL(sb + 24 + 16 * s);
        }
        #pragma unroll
        for (int i = 0; i < SG; ++i) MBAR_INVAL(sb + 80 + 8 * i);
    }
    __syncthreads();
    if (wid == 0) tc_dealloc(tb, 128);
}

// ================= batched output GEMM ======================================
__global__ void __launch_bounds__(288, 1)
out_tc(const float* __restrict__ bo, float* __restrict__ outp) {
    constexpr int NT = 128;
    constexpr int KC = 64;
    constexpr int NC = Hz / KC;
    constexpr int S  = 3;
    constexpr uint32_t STG = 65536;
    constexpr uint32_t OFF = 1024;
    constexpr uint32_t IDESC =
        (8u << 24) | ((NT / 8) << 17) | (2u << 10) | (2u << 7) | (1u << 4);

    extern __shared__ __align__(1024) char smem[];
    const uint32_t sb = smem_u32(smem);
    const int tid = threadIdx.x;
    const int wid = tid >> 5, lid = tid & 31;
    const int m0 = blockIdx.y * 128;
    const int n0 = blockIdx.x * NT;

    const float* Arow = g_hall + (size_t)m0 * Hz;

    if (wid == 0) tc_alloc(sb + 0, 128);
    if (tid == 0) {
        #pragma unroll
        for (int s = 0; s < S; ++s) {
            MBAR_INIT(sb + 16 + 16 * s, 256);
            MBAR_INIT(sb + 24 + 16 * s, 1);
        }
    }
    __syncthreads();
    uint32_t tb;
    asm volatile("ld.shared.b32 %0, [%1];" : "=r"(tb) : "r"(sb + 0));

    if (tid < 256) {
        for (int c = 0; c < NC; ++c) {
            const int s = c % S;
            if (c >= S) MBAR_WAIT(sb + 24 + 16 * s, ((c / S) - 1) & 1);
            const uint32_t base = sb + OFF + s * STG;
            const int k0 = c * KC;
            #pragma unroll
            for (int i = 0; i < 8; ++i) {
                int v = i * 256 + tid;
                int row = v >> 4, kk = (v & 15) << 2;
                uint32_t off = (uint32_t)(row << 7) + ((kk & 31) << 2);
                off ^= (off >> 3) & 0x70;
                CP16(base + (uint32_t)((kk >> 5) * 16384) + off,
                     Arow + (size_t)row * Hz + k0 + kk);
            }
            #pragma unroll
            for (int i = 0; i < 8; ++i) {
                int v = i * 256 + tid;
                int row = v >> 4, kk = (v & 15) << 2;
                uint32_t off = (uint32_t)(row << 7) + ((kk & 31) << 2);
                off ^= (off >> 3) & 0x70;
                uint32_t so = (uint32_t)((kk >> 5) * 16384) + off;
                CP16(base + 32768 + so, g_Wo + (size_t)(n0 + row) * Hz + k0 + kk);
            }
            CPA_ARRIVE(sb + 16 + 16 * s);
        }
    } else if (tid == 256) {
        for (int c = 0; c < NC; ++c) {
            const int s = c % S;
            MBAR_WAIT(sb + 16 + 16 * s, (c / S) & 1);
            FENCE_ASYNC();
            const uint32_t base = sb + OFF + s * STG;
            const uint64_t ad = mkdesc(base);
            const uint64_t bd = mkdesc(base + 32768);
            #pragma unroll
            for (int h = 0; h < 2; ++h)
                #pragma unroll
                for (int q = 0; q < 4; ++q) {
                    uint32_t en = (c | h | q) != 0;
                    mma_tf32(tb, ad + h * 1024 + q * 2,
                             bd + h * 1024 + q * 2, IDESC, en);
                }
            tc_commit(sb + 24 + 16 * s);
        }
    }

    MBAR_WAIT(sb + 24 + 16 * ((NC - 1) % S), ((NC - 1) / S) & 1);
    tc_fence_after();

    if (wid < 8) {
        const int sub = wid & 3, wg = wid >> 2;
        const int m = m0 + sub * 32 + lid;
        const int tt = m >> 9;
        const int bb = m & (Bz - 1);
        float* orow = outp + (size_t)bb * Tz * Oz + (size_t)tt * Oz;
        #pragma unroll
        for (int g = 0; g < 2; ++g) {
            const int nl = wg * 64 + g * 32;
            uint32_t r[32];
            tc_ld32(r, tb + nl);
            tc_wait_ld();
            const int n = n0 + nl;
            const float4* bo4 = (const float4*)(bo + n);
            float4* op = (float4*)(orow + n);
            #pragma unroll
            for (int v = 0; v < 8; ++v) {
                float4 b4 = bo4[v], o;
                o.x = __uint_as_float(r[4 * v + 0]) + b4.x;
                o.y = __uint_as_float(r[4 * v + 1]) + b4.y;
                o.z = __uint_as_float(r[4 * v + 2]) + b4.z;
                o.w = __uint_as_float(r[4 * v + 3]) + b4.w;
                op[v] = o;
            }
        }
    }

    __syncthreads();
    if (tid == 0) {
        #pragma unroll
        for (int s = 0; s < S; ++s) {
            MBAR_INVAL(sb + 16 + 16 * s);
            MBAR_INVAL(sb + 24 + 16 * s);
        }
    }
    __syncthreads();
    if (wid == 0) tc_dealloc(tb, 128);
}

// --------------------------- SIMT projection (once) -------------------------
__global__ void __launch_bounds__(256)
proj_gemm(const float* __restrict__ x,
          const float* __restrict__ W1, const float* __restrict__ W2,
          const float* __restrict__ b1a, const float* __restrict__ b1b,
          const float* __restrict__ b2a, const float* __restrict__ b2b) {
    constexpr int BM = 64, BN = 64, BK = 16, K = Iz;
    __shared__ float As[BK][BM + 4];
    __shared__ float W1s[BK][BN + 4];
    __shared__ float W2s[BK][BN + 4];

    const int tid = threadIdx.x;
    const int m0 = blockIdx.y * BM;
    const int n0 = blockIdx.x * BN;
    const int lr = tid >> 2;
    const int lk = (tid & 3) * 4;
    const int tmm = (tid & 15) * 4;
    const int tnn = (tid >> 4) * 4;

    float acc1[4][4] = {};
    float acc2[4][4] = {};

    for (int k0 = 0; k0 < K; k0 += BK) {
        float4 av = *(const float4*)(x  + (size_t)(m0 + lr) * K + k0 + lk);
        float4 w1 = *(const float4*)(W1 + (size_t)(n0 + lr) * K + k0 + lk);
        float4 w2 = *(const float4*)(W2 + (size_t)(n0 + lr) * K + k0 + lk);
        __syncthreads();
        As [lk + 0][lr] = av.x; As [lk + 1][lr] = av.y;
        As [lk + 2][lr] = av.z; As [lk + 3][lr] = av.w;
        W1s[lk + 0][lr] = w1.x; W1s[lk + 1][lr] = w1.y;
        W1s[lk + 2][lr] = w1.z; W1s[lk + 3][lr] = w1.w;
        W2s[lk + 0][lr] = w2.x; W2s[lk + 1][lr] = w2.y;
        W2s[lk + 2][lr] = w2.z; W2s[lk + 3][lr] = w2.w;
        __syncthreads();
        #pragma unroll
        for (int kk = 0; kk < BK; ++kk) {
            float a[4], u[4], v[4];
            #pragma unroll
            for (int i = 0; i < 4; ++i) a[i] = As[kk][tmm + i];
            #pragma unroll
            for (int j = 0; j < 4; ++j) { u[j] = W1s[kk][tnn + j]; v[j] = W2s[kk][tnn + j]; }
            #pragma unroll
            for (int i = 0; i < 4; ++i)
                #pragma unroll
                for (int j = 0; j < 4; ++j) {
                    acc1[i][j] = fmaf(a[i], u[j], acc1[i][j]);
                    acc2[i][j] = fmaf(a[i], v[j], acc2[i][j]);
                }
        }
    }

    #pragma unroll
    for (int i = 0; i < 4; ++i) {
        const int m = m0 + tmm + i;
        #pragma unroll
        for (int j = 0; j < 4; ++j) {
            const int n = n0 + tnn + j;
            const size_t idx = (size_t)m * Hz + n;
            g_jx[idx] = acc1[i][j] + b1a[n] + b1b[n];
            g_kx[idx] = acc2[i][j] + b2a[n] + b2b[n];
        }
    }
}

// --------------------------- host launcher ----------------------------------
typedef CUresult (*EncodeTiledFn)(
    CUtensorMap*, CUtensorMapDataType, cuuint32_t, void*,
    const cuuint64_t*, const cuuint64_t*, const cuuint32_t*, const cuuint32_t*,
    CUtensorMapInterleave, CUtensorMapSwizzle, CUtensorMapL2promotion,
    CUtensorMapFloatOOBfill);

extern "C" void kernel_launch(void* const* d_in, const int* in_sizes, int n_in,
                              void* d_out, int out_size) {
    const float* x   = (const float*)d_in[0];
    const float* h0  = (const float*)d_in[1];
    const float* Wjx = (const float*)d_in[2];
    const float* bjx = (const float*)d_in[3];
    const float* Wjh = (const float*)d_in[4];
    const float* bjh = (const float*)d_in[5];
    const float* Wkx = (const float*)d_in[6];
    const float* bkx = (const float*)d_in[7];
    const float* Wkh = (const float*)d_in[8];
    const float* bkh = (const float*)d_in[9];
    const float* Wo  = (const float*)d_in[10];
    const float* bo  = (const float*)d_in[11];
    float* out = (float*)d_out;

    EncodeTiledFn encode = nullptr;
    cudaDriverEntryPointQueryResult qr;
    cudaGetDriverEntryPoint("cuTensorMapEncodeTiled", (void**)&encode,
                            cudaEnableDefault, &qr);

    void *pWj = nullptr, *pWk = nullptr;
    cudaGetSymbolAddress(&pWj, g_Wjh);
    cudaGetSymbolAddress(&pWk, g_Wkh);

    CUtensorMap tmWj, tmWk;
    {
        cuuint64_t dims[2]    = {Hz, Hz};
        cuuint64_t strides[1] = {Hz * 4ull};
        cuuint32_t box[2]     = {32, 64};
        cuuint32_t es[2]      = {1, 1};
        encode(&tmWj, CU_TENSOR_MAP_DATA_TYPE_FLOAT32, 2, pWj, dims, strides, box, es,
               CU_TENSOR_MAP_INTERLEAVE_NONE, CU_TENSOR_MAP_SWIZZLE_128B,
               CU_TENSOR_MAP_L2_PROMOTION_L2_128B, CU_TENSOR_MAP_FLOAT_OOB_FILL_NONE);
        encode(&tmWk, CU_TENSOR_MAP_DATA_TYPE_FLOAT32, 2, pWk, dims, strides, box, es,
               CU_TENSOR_MAP_INTERLEAVE_NONE, CU_TENSOR_MAP_SWIZZLE_128B,
               CU_TENSOR_MAP_L2_PROMOTION_L2_128B, CU_TENSOR_MAP_FLOAT_OOB_FILL_NONE);
    }

    cudaMemcpyToSymbolAsync(g_h0, h0, sizeof(float) * Bz * Hz, 0,
                            cudaMemcpyDeviceToDevice, 0);

    reset_flags<<<1, 64>>>();
    round_weights<<<512, 256>>>(Wjh, Wkh, Wo);
    proj_gemm<<<dim3(Hz / 64, Bz / 64), 256>>>(x, Wjx, Wkx, bjx, bjh, bkx, bkh);

    constexpr int SME = 1024 + 3 * 65536;   // 197632
    cudaFuncSetAttribute(rec_persist,
                         cudaFuncAttributeMaxDynamicSharedMemorySize, SME);
    cudaFuncSetAttribute(out_tc,
                         cudaFuncAttributeMaxDynamicSharedMemorySize, SME);

    rec_persist<<<dim3(16, 4), 352, SME>>>(tmWj, tmWk);

    out_tc<<<dim3(Oz / 128, (Tz * Bz) / 128), 288, SME>>>(bo, out);

    cudaMemcpyFromSymbolAsync(out + (size_t)Bz * Tz * Oz, g_hall,
                              sizeof(float) * Bz * Hz,
                              sizeof(float) * (size_t)(Tz - 1) * Bz * Hz,
                              cudaMemcpyDeviceToDevice, 0);
}

// round 15
// speedup vs baseline: 1.2575x; 1.2575x over previous
#include <cuda.h>
#include <cuda_runtime.h>
#include <cstdint>

#define Bz 512
#define Iz 512
#define Hz 1024
#define Oz 512
#define Tz 128

#if defined(__CUDA_ARCH__) && \
    (defined(__CUDA_ARCH_FEAT_SM103_ALL) || defined(__CUDA_ARCH_FEAT_SM100_ALL) || \
     defined(__CUDA_ARCH_SPECIFIC__))
#define HAS_TC5 1
#else
#define HAS_TC5 0
#endif

// --------------------------- device scratch ---------------------------------
__device__ float g_jx[Bz * Hz];
__device__ float g_kx[Bz * Hz];
__device__ float g_h0[Bz * Hz];
__device__ float g_hall[(size_t)Tz * Bz * Hz];
__device__ float g_Wjh[Hz * Hz];
__device__ float g_Wkh[Hz * Hz];
__device__ float g_Wo[Oz * Hz];
__device__ unsigned g_flag[4][16];     // [m-group][n-tile] = completed steps
__device__ unsigned g_wq;              // out work queue

// --------------------------- PTX helpers ------------------------------------
__device__ __forceinline__ uint32_t smem_u32(const void* p) {
    uint32_t a;
    asm("{ .reg .u64 t; cvta.to.shared.u64 t, %1; cvt.u32.u64 %0, t; }"
        : "=r"(a) : "l"(p));
    return a;
}
__device__ __forceinline__ float tf32r(float x) {
    uint32_t u; asm("cvt.rna.tf32.f32 %0, %1;" : "=r"(u) : "f"(x));
    return __uint_as_float(u);
}

#define CP16(dst, src) \
    asm volatile("cp.async.cg.shared.global [%0], [%1], 16;" :: "r"(dst), "l"(src) : "memory")
#define CPA_ARRIVE(mb) \
    asm volatile("cp.async.mbarrier.arrive.noinc.shared::cta.b64 [%0];" :: "r"(mb) : "memory")
#define FENCE_ASYNC() asm volatile("fence.proxy.async.shared::cta;" ::: "memory")

#define MBAR_INIT(mb, cnt) \
    asm volatile("mbarrier.init.shared.b64 [%0], %1;" :: "r"(mb), "r"((uint32_t)(cnt)) : "memory")
#define MBAR_INVAL(mb) \
    asm volatile("mbarrier.inval.shared.b64 [%0];" :: "r"(mb) : "memory")
#define MBAR_EXPECT_TX(mb, bytes) \
    asm volatile("mbarrier.arrive.expect_tx.shared.b64 _, [%0], %1;" \
                 :: "r"(mb), "r"((uint32_t)(bytes)) : "memory")
#define MBAR_ARRIVE(mb) \
    asm volatile("mbarrier.arrive.shared.b64 _, [%0];" :: "r"(mb) : "memory")

#define MBAR_WAIT(mb, par) do {                                                  \
    uint32_t _m = (mb), _p = (par), _d;                                          \
    asm volatile("{\n\t.reg .pred p;\n\t"                                        \
        "mbarrier.try_wait.parity.acquire.cta.shared::cta.b64 p, [%1], %2;\n\t"  \
        "selp.b32 %0, 1, 0, p;\n\t}" : "=r"(_d) : "r"(_m), "r"(_p) : "memory");  \
    if (!_d) {                                                                   \
        asm volatile("{\n\t.reg .pred P1;\n\t"                                   \
        "WL_%=:\n\t"                                                             \
        "mbarrier.try_wait.parity.acquire.cta.shared::cta.b64 P1, [%0], %1, 0x989680;\n\t" \
        "@P1 bra.uni WD_%=;\n\t"                                                 \
        "bra.uni WL_%=;\n\t"                                                     \
        "WD_%=:\n\t}" :: "r"(_m), "r"(_p) : "memory");                           \
    }                                                                            \
} while (0)

#define TMA2D(dst, map, x, y, mb) \
    asm volatile("cp.async.bulk.tensor.2d.shared::cta.global.tile.mbarrier::complete_tx::bytes " \
                 "[%0], [%1, {%2, %3}], [%4];" \
                 :: "r"(dst), "l"(map), "r"((int)(x)), "r"((int)(y)), "r"(mb) \
                 : "memory")

__device__ __forceinline__ void tc_alloc(uint32_t sa, uint32_t n) {
#if HAS_TC5
    asm volatile("tcgen05.alloc.cta_group::1.sync.aligned.shared::cta.b32 [%0], %1;"
                 :: "r"(sa), "r"(n) : "memory");
    asm volatile("tcgen05.relinquish_alloc_permit.cta_group::1.sync.aligned;");
#endif
}
__device__ __forceinline__ void tc_dealloc(uint32_t t, uint32_t n) {
#if HAS_TC5
    asm volatile("tcgen05.dealloc.cta_group::1.sync.aligned.b32 %0, %1;" :: "r"(t), "r"(n));
#endif
}
__device__ __forceinline__ void tc_commit(uint32_t mb) {
#if HAS_TC5
    asm volatile("tcgen05.commit.cta_group::1.mbarrier::arrive::one.shared::cluster.b64 [%0];"
                 :: "r"(mb) : "memory");
#endif
}
__device__ __forceinline__ void tc_fence_after() {
#if HAS_TC5
    asm volatile("tcgen05.fence::after_thread_sync;" ::: "memory");
#endif
}
__device__ __forceinline__ void tc_fence_before() {
#if HAS_TC5
    asm volatile("tcgen05.fence::before_thread_sync;" ::: "memory");
#endif
}
__device__ __forceinline__ void tc_wait_ld() {
#if HAS_TC5
    asm volatile("tcgen05.wait::ld.sync.aligned;" ::: "memory");
#endif
}
__device__ __forceinline__ void tc_ld32(uint32_t* r, uint32_t ta) {
#if HAS_TC5
    asm volatile("tcgen05.ld.sync.aligned.32x32b.x32.b32 "
        "{%0, %1, %2, %3, %4, %5, %6, %7, %8, %9, %10, %11, %12, %13, %14, %15,"
        " %16, %17, %18, %19, %20, %21, %22, %23, %24, %25, %26, %27, %28, %29, %30, %31}, [%32];"
        : "=r"(r[0]),  "=r"(r[1]),  "=r"(r[2]),  "=r"(r[3]),
          "=r"(r[4]),  "=r"(r[5]),  "=r"(r[6]),  "=r"(r[7]),
          "=r"(r[8]),  "=r"(r[9]),  "=r"(r[10]), "=r"(r[11]),
          "=r"(r[12]), "=r"(r[13]), "=r"(r[14]), "=r"(r[15]),
          "=r"(r[16]), "=r"(r[17]), "=r"(r[18]), "=r"(r[19]),
          "=r"(r[20]), "=r"(r[21]), "=r"(r[22]), "=r"(r[23]),
          "=r"(r[24]), "=r"(r[25]), "=r"(r[26]), "=r"(r[27]),
          "=r"(r[28]), "=r"(r[29]), "=r"(r[30]), "=r"(r[31])
        : "r"(ta));
#else
    #pragma unroll
    for (int i = 0; i < 32; ++i) r[i] = 0;
#endif
}
__device__ __forceinline__ void mma_tf32(uint32_t d, uint64_t ad, uint64_t bd,
                                         uint32_t idesc, uint32_t en) {
#if HAS_TC5
    asm volatile(
        "{\n\t.reg .pred p;\n\tsetp.ne.u32 p, %5, 0;\n\t"
        "tcgen05.mma.cta_group::1.kind::tf32 [%0], %1, %2, %3, {%4, %4, %4, %4}, p;\n\t}"
        :: "r"(d), "l"(ad), "l"(bd), "r"(idesc), "r"(0u), "r"(en) : "memory");
#endif
}

__device__ __forceinline__ uint64_t mkdesc(uint32_t addr) {
    constexpr uint64_t BASE =
        (2ull << 61) | (1ull << 46) | (64ull << 32) | (1ull << 16);
    return BASE | ((uint64_t)(addr >> 4) & 0x3FFF);
}

__device__ __forceinline__ float sigm(float x) {
    return 1.0f / (1.0f + __expf(-x));
}

// --------------------------- setup kernels -----------------------------------
__global__ void reset_flags() {
    if (threadIdx.x < 64) g_flag[threadIdx.x >> 4][threadIdx.x & 15] = 0;
    if (threadIdx.x == 64) g_wq = 0;
}

__global__ void round_weights(const float* __restrict__ Wjh,
                              const float* __restrict__ Wkh,
                              const float* __restrict__ Wo) {
    for (int i = blockIdx.x * blockDim.x + threadIdx.x; i < Hz * Hz;
         i += gridDim.x * blockDim.x) {
        g_Wjh[i] = tf32r(Wjh[i]);
        g_Wkh[i] = tf32r(Wkh[i]);
        if (i < Oz * Hz) g_Wo[i] = tf32r(Wo[i]);
    }
}

// ================= FUSED persistent kernel ===================================
// 148 CTAs, ONE launch (single stream; 197KB smem -> 1 CTA/SM -> all resident,
// so the flag-spins can never deadlock):
//   blocks 0-63   : recurrence (R10-proven body; grp = bid>>4, n = bid&15)
//   blocks 64-147 : output GEMM work-queue, consuming g_flag as tiles become
//                   ready. All 352 threads participate in the out loop so
//                   __syncthreads stays uniform.
__global__ void __launch_bounds__(352, 1)
fused_persist(const __grid_constant__ CUtensorMap tmWj,
              const __grid_constant__ CUtensorMap tmWk,
              const float* __restrict__ bo, float* __restrict__ outp) {
    constexpr int KC = 64;
    constexpr int NC = Hz / KC;        // 16 chunks
    constexpr int S  = 3;
    constexpr int SG = 4;
    constexpr uint32_t STG = 65536;
    constexpr uint32_t OFF = 1024;
    constexpr uint32_t IDESC =         // M=128, N=128, tf32
        (8u << 24) | (16u << 17) | (2u << 10) | (2u << 7) | (1u << 4);

    extern __shared__ __align__(1024) char smem[];
    const uint32_t sb = smem_u32(smem);
    const int tid = threadIdx.x;
    const int wid = tid >> 5, lid = tid & 31;
    const int bid = blockIdx.x;

    if (bid < 64) {
        // ======================= RECURRENCE (R10 verbatim) =======================
        const int grp = bid >> 4;
        const int myN = bid & 15;
        const int m0 = grp * 128;
        const int n0 = myN * 64;

        if (wid == 0) tc_alloc(sb + 0, 128);
        if (tid == 0) {
            #pragma unroll
            for (int s = 0; s < S; ++s) {
                MBAR_INIT(sb + 16 + 16 * s, 257);   // full[s]: 256 A + 1 expect_tx
                MBAR_INIT(sb + 24 + 16 * s, 1);     // empty[s]
            }
            #pragma unroll
            for (int i = 0; i < SG; ++i)
                MBAR_INIT(sb + 80 + 8 * i, 1);      // gate[i]
        }
        __syncthreads();
        uint32_t tb;
        asm volatile("ld.shared.b32 %0, [%1];" : "=r"(tb) : "r"(sb + 0));

        if (tid < 256) {
            // ---- A producers + epilogue ----
            const int sub = wid & 3, g = wid >> 2;
            const int m = m0 + sub * 32 + lid;
            const int n = n0 + g * 32;
            const float4* jx4 = (const float4*)(g_jx + (size_t)m * Hz + n);
            const float4* kx4 = (const float4*)(g_kx + (size_t)m * Hz + n);

            float4 hreg[8];
            {
                const float4* h04 = (const float4*)(g_h0 + (size_t)m * Hz + n);
                #pragma unroll
                for (int v = 0; v < 8; ++v) hreg[v] = h04[v];
            }

            for (int t = 0; t < Tz; ++t) {
                const float* Arow = ((t == 0) ? g_h0
                                              : g_hall + (size_t)(t - 1) * Bz * Hz)
                                    + (size_t)m0 * Hz;
                for (int c = 0; c < NC; ++c) {
                    const int C = t * NC + c;
                    MBAR_WAIT(sb + 80 + 8 * (C % SG), (C / SG) & 1);
                    const int s = C % S;
                    if (C >= S) MBAR_WAIT(sb + 24 + 16 * s, ((C / S) - 1) & 1);
                    const uint32_t base = sb + OFF + s * STG;
                    const int k0 = c * KC;
                    #pragma unroll
                    for (int i = 0; i < 8; ++i) {
                        int v = i * 256 + tid;
                        int row = v >> 4, kk = (v & 15) << 2;
                        uint32_t off = (uint32_t)(row << 7) + ((kk & 31) << 2);
                        off ^= (off >> 3) & 0x70;
                        CP16(base + (uint32_t)((kk >> 5) * 16384) + off,
                             Arow + (size_t)row * Hz + k0 + kk);
                    }
                    CPA_ARRIVE(sb + 16 + 16 * s);
                }

                float4 jxv[8], kxv[8];
                #pragma unroll
                for (int v = 0; v < 8; ++v) { jxv[v] = jx4[v]; kxv[v] = kx4[v]; }

                const int CL = t * NC + (NC - 1);
                MBAR_WAIT(sb + 24 + 16 * (CL % S), (CL / S) & 1);
                tc_fence_after();

                uint32_t jr[32], kr[32];
                tc_ld32(jr, tb + g * 32);
                tc_ld32(kr, tb + 64 + g * 32);
                tc_wait_ld();

                float* hop = g_hall + (size_t)t * Bz * Hz + (size_t)m * Hz + n;
                #pragma unroll
                for (int v = 0; v < 8; ++v) {
                    float4 jx = jxv[v], kx = kxv[v], hp = hreg[v], o;
                    {
                        float jg = sigm(jx.x + __uint_as_float(jr[4 * v + 0]));
                        float kg = sigm(kx.x + __uint_as_float(kr[4 * v + 0]));
                        o.x = tf32r(jg + hp.x * (1.0f - jg - kg));
                    }
                    {
                        float jg = sigm(jx.y + __uint_as_float(jr[4 * v + 1]));
                        float kg = sigm(kx.y + __uint_as_float(kr[4 * v + 1]));
                        o.y = tf32r(jg + hp.y * (1.0f - jg - kg));
                    }
                    {
                        float jg = sigm(jx.z + __uint_as_float(jr[4 * v + 2]));
                        float kg = sigm(kx.z + __uint_as_float(kr[4 * v + 2]));
                        o.z = tf32r(jg + hp.z * (1.0f - jg - kg));
                    }
                    {
                        float jg = sigm(jx.w + __uint_as_float(jr[4 * v + 3]));
                        float kg = sigm(kx.w + __uint_as_float(kr[4 * v + 3]));
                        o.w = tf32r(jg + hp.w * (1.0f - jg - kg));
                    }
                    ((float4*)hop)[v] = o;
                    hreg[v] = o;
                }
                tc_fence_before();

                asm volatile("bar.sync 1, 256;" ::: "memory");
                if (tid == 0) {
                    __threadfence();
                    asm volatile("st.release.gpu.global.u32 [%0], %1;"
                                 :: "l"(&g_flag[grp][myN]), "r"((unsigned)(t + 1))
                                 : "memory");
                }
            }
        } else if (tid == 256) {
            // ---- weight TMA producer ----
            for (int t = 0; t < Tz; ++t) {
                for (int c = 0; c < NC; ++c) {
                    const int C = t * NC + c;
                    const int s = C % S;
                    if (C >= S) MBAR_WAIT(sb + 24 + 16 * s, ((C / S) - 1) & 1);
                    const uint32_t base = sb + OFF + s * STG;
                    const uint32_t fb = sb + 16 + 16 * s;
                    const int k0 = c * KC;
                    MBAR_EXPECT_TX(fb, 32768);
                    TMA2D(base + 32768,        &tmWj, k0,      n0, fb);
                    TMA2D(base + 32768 + 8192, &tmWk, k0,      n0, fb);
                    TMA2D(base + 49152,        &tmWj, k0 + 32, n0, fb);
                    TMA2D(base + 49152 + 8192, &tmWk, k0 + 32, n0, fb);
                }
            }
        } else if (tid == 288) {
            // ---- MMA issuer ----
            for (int t = 0; t < Tz; ++t) {
                for (int c = 0; c < NC; ++c) {
                    const int C = t * NC + c;
                    const int s = C % S;
                    MBAR_WAIT(sb + 16 + 16 * s, (C / S) & 1);
                    FENCE_ASYNC();
                    const uint32_t base = sb + OFF + s * STG;
                    #pragma unroll
                    for (int s2 = 0; s2 < 2; ++s2) {
                        const uint64_t ad = mkdesc(base + s2 * 16384);
                        const uint64_t bd = mkdesc(base + 32768 + s2 * 16384);
                        #pragma unroll
                        for (int q = 0; q < 4; ++q) {
                            uint32_t en = (c | s2 | q) != 0;
                            mma_tf32(tb, ad + q * 2, bd + q * 2, IDESC, en);
                        }
                    }
                    tc_commit(sb + 24 + 16 * s);
                }
            }
        } else if (tid == 320) {
            // ---- gate ----
            for (int t = 0; t < Tz; ++t) {
                for (int c = 0; c < NC; ++c) {
                    const int C = t * NC + c;
                    const int s = C % S;
                    if (C >= S) MBAR_WAIT(sb + 24 + 16 * s, ((C / S) - 1) & 1);
                    if (t > 0) {
                        const unsigned* fp = &g_flag[grp][c];
                        unsigned v;
                        do {
                            asm volatile("ld.acquire.gpu.global.u32 %0, [%1];"
                                         : "=r"(v) : "l"(fp) : "memory");
                            if (v < (unsigned)t) __nanosleep(32);
                        } while (v < (unsigned)t);
                    }
                    MBAR_ARRIVE(sb + 80 + 8 * (C % SG));
                }
            }
        }

        __syncthreads();
        if (tid == 0) {
            #pragma unroll
            for (int s = 0; s < S; ++s) {
                MBAR_INVAL(sb + 16 + 16 * s);
                MBAR_INVAL(sb + 24 + 16 * s);
            }
            #pragma unroll
            for (int i = 0; i < SG; ++i) MBAR_INVAL(sb + 80 + 8 * i);
        }
        __syncthreads();
        if (wid == 0) tc_dealloc(tb, 128);
        return;
    }

    // ========================= OUTPUT GEMM (work queue) =========================
    constexpr int NT = 128;
    constexpr int NTILES = (Oz / NT) * ((Tz * Bz) / 128);   // 2048

    if (wid == 0) tc_alloc(sb + 0, 128);
    if (tid == 0) {
        #pragma unroll
        for (int s = 0; s < S; ++s) {
            MBAR_INIT(sb + 16 + 16 * s, 256);
            MBAR_INIT(sb + 24 + 16 * s, 1);
        }
    }
    __syncthreads();
    uint32_t tb;
    asm volatile("ld.shared.b32 %0, [%1];" : "=r"(tb) : "r"(sb + 0));

    int RC = 0;    // running chunk counter (same trajectory in all roles)

    for (;;) {
        if (tid == 0) {
            unsigned w = atomicAdd(&g_wq, 1u);
            if (w < (unsigned)NTILES) {
                const int y = (int)(w >> 2);
                const int t = y >> 2;
                const int grp = y & 3;
                for (int c = 0; c < 16; ++c) {
                    const unsigned* fp = &g_flag[grp][c];
                    unsigned v;
                    do {
                        asm volatile("ld.acquire.gpu.global.u32 %0, [%1];"
                                     : "=r"(v) : "l"(fp) : "memory");
                        if (v < (unsigned)(t + 1)) __nanosleep(256);
                    } while (v < (unsigned)(t + 1));
                }
            }
            asm volatile("st.shared.b32 [%0], %1;" :: "r"(sb + 8), "r"(w) : "memory");
        }
        __syncthreads();
        unsigned w;
        asm volatile("ld.shared.b32 %0, [%1];" : "=r"(w) : "r"(sb + 8));
        if (w >= (unsigned)NTILES) break;
        tc_fence_after();

        const int m0 = (int)(w >> 2) * 128;
        const int n0 = (int)(w & 3) * NT;
        const float* Arow = g_hall + (size_t)m0 * Hz;

        if (tid < 256) {
            for (int c = 0; c < NC; ++c, ++RC) {
                const int s = RC % S;
                if (RC >= S) MBAR_WAIT(sb + 24 + 16 * s, ((RC / S) - 1) & 1);
                const uint32_t base = sb + OFF + s * STG;
                const int k0 = c * KC;
                #pragma unroll
                for (int i = 0; i < 8; ++i) {
                    int v = i * 256 + tid;
                    int row = v >> 4, kk = (v & 15) << 2;
                    uint32_t off = (uint32_t)(row << 7) + ((kk & 31) << 2);
                    off ^= (off >> 3) & 0x70;
                    CP16(base + (uint32_t)((kk >> 5) * 16384) + off,
                         Arow + (size_t)row * Hz + k0 + kk);
                }
                #pragma unroll
                for (int i = 0; i < 8; ++i) {
                    int v = i * 256 + tid;
                    int row = v >> 4, kk = (v & 15) << 2;
                    uint32_t off = (uint32_t)(row << 7) + ((kk & 31) << 2);
                    off ^= (off >> 3) & 0x70;
                    uint32_t so = (uint32_t)((kk >> 5) * 16384) + off;
                    CP16(base + 32768 + so,
                         g_Wo + (size_t)(n0 + row) * Hz + k0 + kk);
                }
                CPA_ARRIVE(sb + 16 + 16 * s);
            }
            const int X = RC - 1;
            MBAR_WAIT(sb + 24 + 16 * (X % S), (X / S) & 1);
            tc_fence_after();
            if (wid < 8) {
                const int sub = wid & 3, wg = wid >> 2;
                const int m = m0 + sub * 32 + lid;
                const int tt = m >> 9;
                const int bb = m & (Bz - 1);
                float* orow = outp + (size_t)bb * Tz * Oz + (size_t)tt * Oz;
                #pragma unroll
                for (int g = 0; g < 2; ++g) {
                    const int nl = wg * 64 + g * 32;
                    uint32_t r[32];
                    tc_ld32(r, tb + nl);
                    tc_wait_ld();
                    const int n = n0 + nl;
                    const float4* bo4 = (const float4*)(bo + n);
                    float4* op = (float4*)(orow + n);
                    #pragma unroll
                    for (int v = 0; v < 8; ++v) {
                        float4 b4 = bo4[v], o;
                        o.x = __uint_as_float(r[4 * v + 0]) + b4.x;
                        o.y = __uint_as_float(r[4 * v + 1]) + b4.y;
                        o.z = __uint_as_float(r[4 * v + 2]) + b4.z;
                        o.w = __uint_as_float(r[4 * v + 3]) + b4.w;
                        op[v] = o;
                    }
                }
            }
            tc_fence_before();
        } else if (tid == 256) {
            for (int c = 0; c < NC; ++c, ++RC) {
                const int s = RC % S;
                MBAR_WAIT(sb + 16 + 16 * s, (RC / S) & 1);
                FENCE_ASYNC();
                const uint32_t base = sb + OFF + s * STG;
                #pragma unroll
                for (int h = 0; h < 2; ++h)
                    #pragma unroll
                    for (int q = 0; q < 4; ++q) {
                        uint32_t en = (c | h | q) != 0;
                        mma_tf32(tb, mkdesc(base) + h * 1024 + q * 2,
                                 mkdesc(base + 32768) + h * 1024 + q * 2,
                                 IDESC, en);
                    }
                tc_commit(sb + 24 + 16 * s);
            }
        } else {
            RC += NC;
        }
        __syncthreads();
    }

    __syncthreads();
    if (tid == 0) {
        #pragma unroll
        for (int s = 0; s < S; ++s) {
            MBAR_INVAL(sb + 16 + 16 * s);
            MBAR_INVAL(sb + 24 + 16 * s);
        }
    }
    __syncthreads();
    if (wid == 0) tc_dealloc(tb, 128);
}

// --------------------------- SIMT projection (once) -------------------------
__global__ void __launch_bounds__(256)
proj_gemm(const float* __restrict__ x,
          const float* __restrict__ W1, const float* __restrict__ W2,
          const float* __restrict__ b1a, const float* __restrict__ b1b,
          const float* __restrict__ b2a, const float* __restrict__ b2b) {
    constexpr int BM = 64, BN = 64, BK = 16, K = Iz;
    __shared__ float As[BK][BM + 4];
    __shared__ float W1s[BK][BN + 4];
    __shared__ float W2s[BK][BN + 4];

    const int tid = threadIdx.x;
    const int m0 = blockIdx.y * BM;
    const int n0 = blockIdx.x * BN;
    const int lr = tid >> 2;
    const int lk = (tid & 3) * 4;
    const int tmm = (tid & 15) * 4;
    const int tnn = (tid >> 4) * 4;

    float acc1[4][4] = {};
    float acc2[4][4] = {};

    for (int k0 = 0; k0 < K; k0 += BK) {
        float4 av = *(const float4*)(x  + (size_t)(m0 + lr) * K + k0 + lk);
        float4 w1 = *(const float4*)(W1 + (size_t)(n0 + lr) * K + k0 + lk);
        float4 w2 = *(const float4*)(W2 + (size_t)(n0 + lr) * K + k0 + lk);
        __syncthreads();
        As [lk + 0][lr] = av.x; As [lk + 1][lr] = av.y;
        As [lk + 2][lr] = av.z; As [lk + 3][lr] = av.w;
        W1s[lk + 0][lr] = w1.x; W1s[lk + 1][lr] = w1.y;
        W1s[lk + 2][lr] = w1.z; W1s[lk + 3][lr] = w1.w;
        W2s[lk + 0][lr] = w2.x; W2s[lk + 1][lr] = w2.y;
        W2s[lk + 2][lr] = w2.z; W2s[lk + 3][lr] = w2.w;
        __syncthreads();
        #pragma unroll
        for (int kk = 0; kk < BK; ++kk) {
            float a[4], u[4], v[4];
            #pragma unroll
            for (int i = 0; i < 4; ++i) a[i] = As[kk][tmm + i];
            #pragma unroll
            for (int j = 0; j < 4; ++j) { u[j] = W1s[kk][tnn + j]; v[j] = W2s[kk][tnn + j]; }
            #pragma unroll
            for (int i = 0; i < 4; ++i)
                #pragma unroll
                for (int j = 0; j < 4; ++j) {
                    acc1[i][j] = fmaf(a[i], u[j], acc1[i][j]);
                    acc2[i][j] = fmaf(a[i], v[j], acc2[i][j]);
                }
        }
    }

    #pragma unroll
    for (int i = 0; i < 4; ++i) {
        const int m = m0 + tmm + i;
        #pragma unroll
        for (int j = 0; j < 4; ++j) {
            const int n = n0 + tnn + j;
            const size_t idx = (size_t)m * Hz + n;
            g_jx[idx] = acc1[i][j] + b1a[n] + b1b[n];
            g_kx[idx] = acc2[i][j] + b2a[n] + b2b[n];
        }
    }
}

// --------------------------- host launcher ----------------------------------
typedef CUresult (*EncodeTiledFn)(
    CUtensorMap*, CUtensorMapDataType, cuuint32_t, void*,
    const cuuint64_t*, const cuuint64_t*, const cuuint32_t*, const cuuint32_t*,
    CUtensorMapInterleave, CUtensorMapSwizzle, CUtensorMapL2promotion,
    CUtensorMapFloatOOBfill);

extern "C" void kernel_launch(void* const* d_in, const int* in_sizes, int n_in,
                              void* d_out, int out_size) {
    const float* x   = (const float*)d_in[0];
    const float* h0  = (const float*)d_in[1];
    const float* Wjx = (const float*)d_in[2];
    const float* bjx = (const float*)d_in[3];
    const float* Wjh = (const float*)d_in[4];
    const float* bjh = (const float*)d_in[5];
    const float* Wkx = (const float*)d_in[6];
    const float* bkx = (const float*)d_in[7];
    const float* Wkh = (const float*)d_in[8];
    const float* bkh = (const float*)d_in[9];
    const float* Wo  = (const float*)d_in[10];
    const float* bo  = (const float*)d_in[11];
    float* out = (float*)d_out;

    EncodeTiledFn encode = nullptr;
    cudaDriverEntryPointQueryResult qr;
    cudaGetDriverEntryPoint("cuTensorMapEncodeTiled", (void**)&encode,
                            cudaEnableDefault, &qr);

    void *pWj = nullptr, *pWk = nullptr;
    cudaGetSymbolAddress(&pWj, g_Wjh);
    cudaGetSymbolAddress(&pWk, g_Wkh);

    CUtensorMap tmWj, tmWk;
    {
        cuuint64_t dims[2]    = {Hz, Hz};
        cuuint64_t strides[1] = {Hz * 4ull};
        cuuint32_t box[2]     = {32, 64};
        cuuint32_t es[2]      = {1, 1};
        encode(&tmWj, CU_TENSOR_MAP_DATA_TYPE_FLOAT32, 2, pWj, dims, strides, box, es,
               CU_TENSOR_MAP_INTERLEAVE_NONE, CU_TENSOR_MAP_SWIZZLE_128B,
               CU_TENSOR_MAP_L2_PROMOTION_L2_128B, CU_TENSOR_MAP_FLOAT_OOB_FILL_NONE);
        encode(&tmWk, CU_TENSOR_MAP_DATA_TYPE_FLOAT32, 2, pWk, dims, strides, box, es,
               CU_TENSOR_MAP_INTERLEAVE_NONE, CU_TENSOR_MAP_SWIZZLE_128B,
               CU_TENSOR_MAP_L2_PROMOTION_L2_128B, CU_TENSOR_MAP_FLOAT_OOB_FILL_NONE);
    }

    cudaMemcpyToSymbolAsync(g_h0, h0, sizeof(float) * Bz * Hz, 0,
                            cudaMemcpyDeviceToDevice, 0);

    reset_flags<<<1, 128>>>();
    round_weights<<<512, 256>>>(Wjh, Wkh, Wo);
    proj_gemm<<<dim3(Hz / 64, Bz / 64), 256>>>(x, Wjx, Wkx, bjx, bjh, bkx, bkh);

    constexpr int SME = 1024 + 3 * 65536;   // 197632 -> 1 CTA/SM
    cudaFuncSetAttribute(fused_persist,
                         cudaFuncAttributeMaxDynamicSharedMemorySize, SME);

    // ONE launch: 64 recurrence CTAs + 84 output CTAs, all co-resident.
    fused_persist<<<148, 352, SME>>>(tmWj, tmWk, bo, out);

    cudaMemcpyFromSymbolAsync(out + (size_t)Bz * Tz * Oz, g_hall,
                              sizeof(float) * Bz * Hz,
                              sizeof(float) * (size_t)(Tz - 1) * Bz * Hz,
                              cudaMemcpyDeviceToDevice, 0);
}